// round 17
// baseline (speedup 1.0000x reference)
#include <cuda_runtime.h>
#include <cuda_fp16.h>

// LSTM B=2048, T=512, LATENT=18, HID=32, gates (i,f,g,o), 4H=128.
// R17 = third submission of R15 (two infra flakes; never executed).
// R14 base (split-gate warp pairing, best 364.7us) with:
//  (1) K repacked 192->160 (z-sections are 18 wide, not 32):
//      kk 0-31 h16|32-63 hr|64-81 z16|82-99 zr|100-131 h16res|132-149 z16res|
//      150-159 zero.  KS=10. Proj live k-steps {0,1,2,3,6,7,8}.
//  (2) paired-rcp pointwise with |x|-bounded denominators (all in (1,2]):
//      sigmoid=(x>=0?1:u)*rcp(1+u), u=e^-|x|; tanh=copysign((1-u)*rcp(1+u),x),
//      u=e^-2|x|; rcps fused pairwise via rcp(dA*dB). 30 MUFU/thread vs 40.
// 128 blocks x 256 threads. Warps 0-3: gates i,g + pointwise; warps 4-7:
// gates f,o (STS to Cs) + proj tiles (4-6) + z staging.

#define NB 2048
#define NT 512
#define NL 18
#define NH 32
#define KS 10          // k-steps of 16 (K=160)
#define ASTR 200       // half stride of A rows (conflict-free: bank=4*gr+tc)
#define CSTR 136       // float stride of Cs rows

#define L2E 1.4426950408889634f

typedef unsigned int u32;

__device__ __forceinline__ float ex2(float x) {
    float r; asm("ex2.approx.f32 %0,%1;" : "=f"(r) : "f"(x)); return r;
}
__device__ __forceinline__ float rcpa(float x) {
    float r; asm("rcp.approx.f32 %0,%1;" : "=f"(r) : "f"(x)); return r;
}
__device__ __forceinline__ u32 h2u32(__half a, __half b) {
    __half2 hv = __halves2half2(a, b);
    return *reinterpret_cast<u32*>(&hv);
}
__device__ __forceinline__ void mma16816(float d[4], const u32 a[4], const u32 b[2]) {
    asm volatile(
        "mma.sync.aligned.m16n8k16.row.col.f32.f16.f16.f32 "
        "{%0,%1,%2,%3}, {%4,%5,%6,%7}, {%8,%9}, {%0,%1,%2,%3};"
        : "+f"(d[0]), "+f"(d[1]), "+f"(d[2]), "+f"(d[3])
        : "r"(a[0]), "r"(a[1]), "r"(a[2]), "r"(a[3]), "r"(b[0]), "r"(b[1]));
}

// Gate B_eff[kk][n] for the K=160 layout.
__device__ __forceinline__ __half w16eff(const float* Whh, const float* Wih,
                                         int n, int kk) {
    float w;
    bool res = false;
    if (kk < 32)        w = Whh[n * NH + kk];
    else if (kk < 64)   w = Whh[n * NH + (kk - 32)];
    else if (kk < 82)   w = Wih[n * NL + (kk - 64)];
    else if (kk < 100)  w = Wih[n * NL + (kk - 82)];
    else if (kk < 132)  { w = Whh[n * NH + (kk - 100)]; res = true; }
    else if (kk < 150)  { w = Wih[n * NL + (kk - 132)]; res = true; }
    else return __float2half_rn(0.f);
    __half h = __float2half_rn(w);
    if (!res) return h;
    return __float2half_rn(w - __half2float(h));
}

// Projection B_eff[kk][m] for the K=160 layout.
__device__ __forceinline__ __half wout_eff(const float* Wout, int m, int kk) {
    if (m >= NL) return __float2half_rn(0.f);
    float w; bool res = false;
    if (kk < 32)        w = Wout[m * NH + kk];
    else if (kk < 64)   w = Wout[m * NH + (kk - 32)];
    else if (kk < 100)  return __float2half_rn(0.f);
    else if (kk < 132)  { w = Wout[m * NH + (kk - 100)]; res = true; }
    else return __float2half_rn(0.f);
    __half h = __float2half_rn(w);
    if (!res) return h;
    return __float2half_rn(w - __half2float(h));
}

__global__ __launch_bounds__(256, 1)
void lstm_fused_tc(const float* __restrict__ z,
                   const float* __restrict__ Wih,
                   const float* __restrict__ Whh,
                   const float* __restrict__ bih,
                   const float* __restrict__ bhh,
                   const float* __restrict__ Wout,
                   const float* __restrict__ bout,
                   float* __restrict__ out)
{
    __shared__ __half As[16][ASTR];
    __shared__ float  Cs[16][CSTR];   // cols 32-63 (f) and 96-127 (o)

    const int tid  = threadIdx.x;
    const int warp = tid >> 5;
    const int lane = tid & 31;
    const int gr   = lane >> 2;
    const int tc   = lane & 3;
    const int be   = blockIdx.x * 16;
    const int ws   = warp & 3;
    const int j0   = 8 * ws + 2 * tc;
    const bool loW = warp < 4;

    // ---- B fragments: warps 0-3 gates (i,g); warps 4-7 gates (f,o) ----
    u32 Bf[2][KS][2];
    {
        int g0 = loW ? 0 : 1;
        int g1 = loW ? 2 : 3;
        int n0 = 32 * g0 + 8 * ws + gr;
        int n1 = 32 * g1 + 8 * ws + gr;
        #pragma unroll
        for (int s = 0; s < KS; s++) {
            int k0 = 16 * s + 2 * tc;
            Bf[0][s][0] = h2u32(w16eff(Whh, Wih, n0, k0),
                                w16eff(Whh, Wih, n0, k0 + 1));
            Bf[0][s][1] = h2u32(w16eff(Whh, Wih, n0, k0 + 8),
                                w16eff(Whh, Wih, n0, k0 + 9));
            Bf[1][s][0] = h2u32(w16eff(Whh, Wih, n1, k0),
                                w16eff(Whh, Wih, n1, k0 + 1));
            Bf[1][s][1] = h2u32(w16eff(Whh, Wih, n1, k0 + 8),
                                w16eff(Whh, Wih, n1, k0 + 9));
        }
    }
    float bb[2][2];
    {
        int g0 = loW ? 0 : 1;
        int g1 = loW ? 2 : 3;
        bb[0][0] = bih[32 * g0 + j0]     + bhh[32 * g0 + j0];
        bb[0][1] = bih[32 * g0 + j0 + 1] + bhh[32 * g0 + j0 + 1];
        bb[1][0] = bih[32 * g1 + j0]     + bhh[32 * g1 + j0];
        bb[1][1] = bih[32 * g1 + j0 + 1] + bhh[32 * g1 + j0 + 1];
    }

    // ---- projection fragments (warps 4..6), live k-steps {0,1,2,3,6,7,8} ----
    u32 Bp[7][2];
    float bp0 = 0.f, bp1 = 0.f;
    const int wp = warp - 4;
    const int mc = (wp >= 0) ? 8 * wp + 2 * tc : 0;
    const bool doProj = (!loW) && wp < 3 && mc < NL;
    if (!loW && wp < 3) {
        int m = 8 * wp + gr;
        const int lives[7] = {0, 1, 2, 3, 6, 7, 8};
        #pragma unroll
        for (int i = 0; i < 7; i++) {
            int k0 = 16 * lives[i] + 2 * tc;
            Bp[i][0] = h2u32(wout_eff(Wout, m, k0),     wout_eff(Wout, m, k0 + 1));
            Bp[i][1] = h2u32(wout_eff(Wout, m, k0 + 8), wout_eff(Wout, m, k0 + 9));
        }
        if (mc < NL) { bp0 = bout[mc]; bp1 = bout[mc + 1]; }
    }

    // ---- zero A buffer (h=0; covers padding cols 150-159 forever) ----
    for (int i = tid; i < 16 * (ASTR / 2); i += 256)
        ((u32*)As)[i] = 0u;
    __syncthreads();

    // z staging on warps 4-7: slots stid and stid+128 (<144)
    const int  stid = tid - 128;
    const int  zr0 = (stid >= 0) ? stid / 9 : 0;
    const int  zc0 = (stid >= 0) ? 2 * (stid % 9) : 0;
    const int  zr1 = (stid >= 0) ? (stid + 128) / 9 : 0;
    const int  zc1 = (stid >= 0) ? 2 * ((stid + 128) % 9) : 0;
    const bool zv0 = stid >= 0;
    const bool zv1 = stid >= 0 && (stid + 128) < 144;

    float2 zn0 = make_float2(0.f, 0.f), zn1 = make_float2(0.f, 0.f);
    if (zv0) {
        float2 v = *(const float2*)(z + ((size_t)(be + zr0) * NT + 0) * NL + zc0);
        __half2 z16 = __floats2half2_rn(v.x, v.y);
        float2 zb = __half22float2(z16);
        __half2 zr = __floats2half2_rn(v.x - zb.x, v.y - zb.y);
        *(__half2*)&As[zr0][64 + zc0]  = z16;
        *(__half2*)&As[zr0][132 + zc0] = z16;
        *(__half2*)&As[zr0][82 + zc0]  = zr;
        zn0 = *(const float2*)(z + ((size_t)(be + zr0) * NT + 1) * NL + zc0);
    }
    if (zv1) {
        float2 v = *(const float2*)(z + ((size_t)(be + zr1) * NT + 0) * NL + zc1);
        __half2 z16 = __floats2half2_rn(v.x, v.y);
        float2 zb = __half22float2(z16);
        __half2 zr = __floats2half2_rn(v.x - zb.x, v.y - zb.y);
        *(__half2*)&As[zr1][64 + zc1]  = z16;
        *(__half2*)&As[zr1][132 + zc1] = z16;
        *(__half2*)&As[zr1][82 + zc1]  = zr;
        zn1 = *(const float2*)(z + ((size_t)(be + zr1) * NT + 1) * NL + zc1);
    }
    __syncthreads();

    float cst[4] = {0.f, 0.f, 0.f, 0.f};
    float hv[4]  = {0.f, 0.f, 0.f, 0.f};

    for (int t = 0; t <= NT; t++) {
        // ---- phase 1: MMA ----
        float d0[4] = {bb[0][0], bb[0][1], bb[0][0], bb[0][1]};
        float d1[4] = {bb[1][0], bb[1][1], bb[1][0], bb[1][1]};
        float dp[4] = {bp0, bp1, bp0, bp1};

        #pragma unroll
        for (int s = 0; s < KS; s++) {
            u32 a[4];
            int k0 = 16 * s + 2 * tc;
            a[0] = *(const u32*)&As[gr][k0];
            a[1] = *(const u32*)&As[gr + 8][k0];
            a[2] = *(const u32*)&As[gr][k0 + 8];
            a[3] = *(const u32*)&As[gr + 8][k0 + 8];
            mma16816(d0, a, Bf[0][s]);
            mma16816(d1, a, Bf[1][s]);
            if (!loW && wp < 3) {
                if (s < 4)       mma16816(dp, a, Bp[s]);
                else if (s == 6) mma16816(dp, a, Bp[4]);
                else if (s == 7) mma16816(dp, a, Bp[5]);
                else if (s == 8) mma16816(dp, a, Bp[6]);
            }
        }

        if (!loW) {
            *(float2*)&Cs[gr][32 + j0]     = make_float2(d0[0], d0[1]);
            *(float2*)&Cs[gr + 8][32 + j0] = make_float2(d0[2], d0[3]);
            *(float2*)&Cs[gr][96 + j0]     = make_float2(d1[0], d1[1]);
            *(float2*)&Cs[gr + 8][96 + j0] = make_float2(d1[2], d1[3]);
            if (t >= 1 && doProj) {
                *(float2*)(out + ((size_t)(be + gr)     * NT + (t - 1)) * NL + mc) =
                    make_float2(dp[0], dp[1]);
                *(float2*)(out + ((size_t)(be + gr + 8) * NT + (t - 1)) * NL + mc) =
                    make_float2(dp[2], dp[3]);
            }
        }
        __syncthreads();   // bar1

        if (t < NT) {
            if (loW) {
                float2 f01 = *(const float2*)&Cs[gr][32 + j0];
                float2 f23 = *(const float2*)&Cs[gr + 8][32 + j0];
                float2 o01 = *(const float2*)&Cs[gr][96 + j0];
                float2 o23 = *(const float2*)&Cs[gr + 8][96 + j0];
                float fq[4] = {f01.x, f01.y, f23.x, f23.y};
                float oq[4] = {o01.x, o01.y, o23.x, o23.y};
                float oos[4];

                // pointwise with paired rcp, all denominators in (1,2]
                #pragma unroll
                for (int q = 0; q < 4; q++) {
                    float di = d0[q], dg = d1[q], df = fq[q], dq = oq[q];
                    float ui = ex2(fabsf(di) * -L2E);
                    float uf = ex2(fabsf(df) * -L2E);
                    float ug = ex2(fabsf(dg) * (-2.0f * L2E));
                    float uo = ex2(fabsf(dq) * -L2E);
                    float Di = 1.f + ui, Df = 1.f + uf;
                    float Dg = 1.f + ug, Do = 1.f + uo;
                    float rA = rcpa(Di * Df);
                    float rB = rcpa(Dg * Do);
                    float ii = ((di >= 0.f) ? 1.f : ui) * (rA * Df);
                    float ff = ((df >= 0.f) ? 1.f : uf) * (rA * Di);
                    float oo = ((dq >= 0.f) ? 1.f : uo) * (rB * Dg);
                    float g2 = copysignf((1.f - ug) * (rB * Do), dg);
                    cst[q] = ff * cst[q] + ii * g2;
                    oos[q] = oo;
                }
                // tanh(c) with cross-q paired rcp
                {
                    float uc0 = ex2(fabsf(cst[0]) * (-2.0f * L2E));
                    float uc1 = ex2(fabsf(cst[1]) * (-2.0f * L2E));
                    float uc2 = ex2(fabsf(cst[2]) * (-2.0f * L2E));
                    float uc3 = ex2(fabsf(cst[3]) * (-2.0f * L2E));
                    float D0 = 1.f + uc0, D1 = 1.f + uc1;
                    float D2 = 1.f + uc2, D3 = 1.f + uc3;
                    float rC = rcpa(D0 * D1);
                    float rD = rcpa(D2 * D3);
                    hv[0] = oos[0] * copysignf((1.f - uc0) * (rC * D1), cst[0]);
                    hv[1] = oos[1] * copysignf((1.f - uc1) * (rC * D0), cst[1]);
                    hv[2] = oos[2] * copysignf((1.f - uc2) * (rD * D3), cst[2]);
                    hv[3] = oos[3] * copysignf((1.f - uc3) * (rD * D2), cst[3]);
                }

                // h -> fp16 + residual into A (rows gr, gr+8)
                {
                    __half2 h16 = __floats2half2_rn(hv[0], hv[1]);
                    float2 hb = __half22float2(h16);
                    __half2 hr = __floats2half2_rn(hv[0] - hb.x, hv[1] - hb.y);
                    *(__half2*)&As[gr][0   + j0] = h16;
                    *(__half2*)&As[gr][100 + j0] = h16;
                    *(__half2*)&As[gr][32  + j0] = hr;
                }
                {
                    __half2 h16 = __floats2half2_rn(hv[2], hv[3]);
                    float2 hb = __half22float2(h16);
                    __half2 hr = __floats2half2_rn(hv[2] - hb.x, hv[3] - hb.y);
                    *(__half2*)&As[gr + 8][0   + j0] = h16;
                    *(__half2*)&As[gr + 8][100 + j0] = h16;
                    *(__half2*)&As[gr + 8][32  + j0] = hr;
                }
            } else if (t + 1 < NT) {
                // warps 4-7: stage z(t+1), prefetch z(t+2)
                if (zv0) {
                    __half2 z16 = __floats2half2_rn(zn0.x, zn0.y);
                    float2 zb = __half22float2(z16);
                    __half2 zr = __floats2half2_rn(zn0.x - zb.x, zn0.y - zb.y);
                    *(__half2*)&As[zr0][64 + zc0]  = z16;
                    *(__half2*)&As[zr0][132 + zc0] = z16;
                    *(__half2*)&As[zr0][82 + zc0]  = zr;
                    if (t + 2 < NT)
                        zn0 = *(const float2*)(z + ((size_t)(be + zr0) * NT + t + 2) * NL + zc0);
                }
                if (zv1) {
                    __half2 z16 = __floats2half2_rn(zn1.x, zn1.y);
                    float2 zb = __half22float2(z16);
                    __half2 zr = __floats2half2_rn(zn1.x - zb.x, zn1.y - zb.y);
                    *(__half2*)&As[zr1][64 + zc1]  = z16;
                    *(__half2*)&As[zr1][132 + zc1] = z16;
                    *(__half2*)&As[zr1][82 + zc1]  = zr;
                    if (t + 2 < NT)
                        zn1 = *(const float2*)(z + ((size_t)(be + zr1) * NT + t + 2) * NL + zc1);
                }
            }
        }
        __syncthreads();   // bar2
    }

    // out layout: [z_pred (B*T*18) | h_n (B*32) | c_n (B*32)]
    if (loW) {
        float* hOut = out + (size_t)NB * NT * NL;
        float* cOut = hOut + (size_t)NB * NH;
        *(float2*)&hOut[(size_t)(be + gr)     * NH + j0] = make_float2(hv[0], hv[1]);
        *(float2*)&hOut[(size_t)(be + gr + 8) * NH + j0] = make_float2(hv[2], hv[3]);
        *(float2*)&cOut[(size_t)(be + gr)     * NH + j0] = make_float2(cst[0], cst[1]);
        *(float2*)&cOut[(size_t)(be + gr + 8) * NH + j0] = make_float2(cst[2], cst[3]);
    }
}

extern "C" void kernel_launch(void* const* d_in, const int* in_sizes, int n_in,
                              void* d_out, int out_size)
{
    const float* z    = (const float*)d_in[0];
    const float* Wih  = (const float*)d_in[1];
    const float* Whh  = (const float*)d_in[2];
    const float* bih  = (const float*)d_in[3];
    const float* bhh  = (const float*)d_in[4];
    const float* Wout = (const float*)d_in[5];
    const float* bout = (const float*)d_in[6];
    float* out = (float*)d_out;

    lstm_fused_tc<<<NB / 16, 256>>>(z, Wih, Whh, bih, bhh, Wout, bout, out);
}